// round 15
// baseline (speedup 1.0000x reference)
#include <cuda_runtime.h>
#include <math.h>
#include <stdint.h>

#define B_   32
#define S_   64
#define E_   512
#define H_   1024
#define V_   32000
#define G3H  (3 * H_)
#define NTOK (B_ * S_)
#define BH   (B_ * H_)
#define NCTA 128

// ---------------- scratch (device globals; no allocation allowed) ----------------
__device__ float g_ex[NTOK * E_];
__device__ float g_dx[NTOK * E_];
__device__ float g_xgA[NTOK * G3H];
__device__ float g_xgB[NTOK * G3H];
__device__ float g_seqA[NTOK * H_];
__device__ float g_seqB[NTOK * H_];
__device__ float g_h[8][BH];
__device__ float g_AT[NTOK * H_];          // transposed activations [K][M]
__device__ float g_WFC[(size_t)V_ * H_];   // repacked fcW: [2][V][512]
__device__ float g_W2a[(size_t)G3H * H_];  // repacked eW1i: [2][3072][512]
__device__ float g_W2b[(size_t)G3H * H_];  // repacked dW1i: [2][3072][512]

// grid-barrier state (zero-init; even barrier count per launch -> self-restoring)
__device__ int g_bar_count;
__device__ int g_bar_sense;

// ---------------- embedding gather ----------------
__global__ void embed_kernel(const int* __restrict__ idx,
                             const float* __restrict__ emb,
                             float* __restrict__ out) {
    int tok = blockIdx.x;
    int row = idx[tok];
    const float4* src = (const float4*)(emb + (size_t)row * E_);
    float4* dst = (float4*)(out + (size_t)tok * E_);
    for (int i = threadIdx.x; i < E_ / 4; i += blockDim.x) dst[i] = src[i];
}

// ---------------- transpose: out[C][R] = in[R][C]^T ----------------
__global__ __launch_bounds__(256)
void transpose_kernel(const float* __restrict__ in, float* __restrict__ out,
                      int R, int C) {
    __shared__ float t[32][33];
    const int c0 = blockIdx.x * 32;
    const int r0 = blockIdx.y * 32;
    const int x = threadIdx.x;
    const int y = threadIdx.y;
#pragma unroll
    for (int i = 0; i < 32; i += 8)
        t[y + i][x] = in[(size_t)(r0 + y + i) * C + c0 + x];
    __syncthreads();
#pragma unroll
    for (int i = 0; i < 32; i += 8)
        out[(size_t)(c0 + y + i) * R + r0 + x] = t[x][y + i];
}

// ---------------- repack W[N][1024] -> [2][N][512] ----------------
__global__ __launch_bounds__(256)
void repack_kernel(const float* __restrict__ in, float* __restrict__ out,
                   int N, int K) {
    size_t i = (size_t)blockIdx.x * 256 + threadIdx.x;   // float4 index
    float4 v = ((const float4*)in)[i];
    int perRow = K >> 2;
    int n = (int)(i / perRow);
    int k = (int)(i % perRow) << 2;
    int Kh = K >> 1;
    int h = k >= Kh;
    *(float4*)(out + (size_t)h * N * Kh + (size_t)n * Kh + (k - h * Kh)) = v;
}

// ---------------- GEMM (76 regs; 29-32 TF/s in measured regimes) ----------------
#define GKT 128
#define GEMM_SMEM (GKT * 128 * 4)

__global__ __launch_bounds__(256)
void gemm_ls_kernel(const float* __restrict__ AT,
                    const float* __restrict__ W,
                    const float* __restrict__ bias,
                    float* __restrict__ C,
                    int M, int N, int Kc, int Kw, int accum) {
    extern __shared__ float As[];   // [GKT][128]

    const int tid  = threadIdx.x;
    const int warp = tid >> 5;
    const int lane = tid & 31;
    const int bm = blockIdx.x * 128;
    const int bn = blockIdx.y * 64;
    const int n0 = bn + warp * 8;
    const int ml = lane * 4;

    float acc[8][4];
#pragma unroll
    for (int i = 0; i < 8; i++)
#pragma unroll
        for (int m = 0; m < 4; m++) acc[i][m] = 0.f;

    const int srow = tid >> 5;
    const int scol = lane << 2;

    const float* w0p = W + (size_t)(n0 + 0) * Kw;
    const float* w1p = W + (size_t)(n0 + 1) * Kw;
    const float* w2p = W + (size_t)(n0 + 2) * Kw;
    const float* w3p = W + (size_t)(n0 + 3) * Kw;
    const float* w4p = W + (size_t)(n0 + 4) * Kw;
    const float* w5p = W + (size_t)(n0 + 5) * Kw;
    const float* w6p = W + (size_t)(n0 + 6) * Kw;
    const float* w7p = W + (size_t)(n0 + 7) * Kw;

    for (int kt = 0; kt < Kc; kt += GKT) {
        __syncthreads();
#pragma unroll
        for (int i = 0; i < 16; i++) {
            int r = srow + i * 8;
            *(float4*)&As[r * 128 + scol] =
                *(const float4*)&AT[(size_t)(kt + r) * M + bm + scol];
        }
        __syncthreads();

#pragma unroll 2
        for (int k4 = 0; k4 < GKT; k4 += 4) {
            float a0[4], a1[4], a2[4], a3[4];
            *(float4*)a0 = *(const float4*)&As[(k4 + 0) * 128 + ml];
            *(float4*)a1 = *(const float4*)&As[(k4 + 1) * 128 + ml];
            *(float4*)a2 = *(const float4*)&As[(k4 + 2) * 128 + ml];
            *(float4*)a3 = *(const float4*)&As[(k4 + 3) * 128 + ml];
            const int ko = kt + k4;

            float4 w0 = __ldg((const float4*)(w0p + ko));
            float4 w1 = __ldg((const float4*)(w1p + ko));
            float4 w2 = __ldg((const float4*)(w2p + ko));
            float4 w3 = __ldg((const float4*)(w3p + ko));
#pragma unroll
            for (int m = 0; m < 4; m++) {
                acc[0][m] += w0.x * a0[m] + w0.y * a1[m] + w0.z * a2[m] + w0.w * a3[m];
                acc[1][m] += w1.x * a0[m] + w1.y * a1[m] + w1.z * a2[m] + w1.w * a3[m];
                acc[2][m] += w2.x * a0[m] + w2.y * a1[m] + w2.z * a2[m] + w2.w * a3[m];
                acc[3][m] += w3.x * a0[m] + w3.y * a1[m] + w3.z * a2[m] + w3.w * a3[m];
            }
            float4 w4 = __ldg((const float4*)(w4p + ko));
            float4 w5 = __ldg((const float4*)(w5p + ko));
            float4 w6 = __ldg((const float4*)(w6p + ko));
            float4 w7 = __ldg((const float4*)(w7p + ko));
#pragma unroll
            for (int m = 0; m < 4; m++) {
                acc[4][m] += w4.x * a0[m] + w4.y * a1[m] + w4.z * a2[m] + w4.w * a3[m];
                acc[5][m] += w5.x * a0[m] + w5.y * a1[m] + w5.z * a2[m] + w5.w * a3[m];
                acc[6][m] += w6.x * a0[m] + w6.y * a1[m] + w6.z * a2[m] + w6.w * a3[m];
                acc[7][m] += w7.x * a0[m] + w7.y * a1[m] + w7.z * a2[m] + w7.w * a3[m];
            }
        }
    }

    if (!accum) {
        float4 bv0 = *(const float4*)(bias + n0);
        float4 bv1 = *(const float4*)(bias + n0 + 4);
#pragma unroll
        for (int m = 0; m < 4; m++) {
            int mr = bm + ml + m;
            float4 o0, o1;
            o0.x = acc[0][m] + bv0.x; o0.y = acc[1][m] + bv0.y;
            o0.z = acc[2][m] + bv0.z; o0.w = acc[3][m] + bv0.w;
            o1.x = acc[4][m] + bv1.x; o1.y = acc[5][m] + bv1.y;
            o1.z = acc[6][m] + bv1.z; o1.w = acc[7][m] + bv1.w;
            *(float4*)(C + (size_t)mr * N + n0)     = o0;
            *(float4*)(C + (size_t)mr * N + n0 + 4) = o1;
        }
    } else {
#pragma unroll
        for (int m = 0; m < 4; m++) {
            int mr = bm + ml + m;
            float4 c0 = *(const float4*)(C + (size_t)mr * N + n0);
            float4 c1 = *(const float4*)(C + (size_t)mr * N + n0 + 4);
            c0.x += acc[0][m]; c0.y += acc[1][m];
            c0.z += acc[2][m]; c0.w += acc[3][m];
            c1.x += acc[4][m]; c1.y += acc[5][m];
            c1.z += acc[6][m]; c1.w += acc[7][m];
            *(float4*)(C + (size_t)mr * N + n0)     = c0;
            *(float4*)(C + (size_t)mr * N + n0 + 4) = c1;
        }
    }
}

// ---------------- persistent GRU scan (R14, measured -4.6ms win) ----------------
__device__ __forceinline__ void grid_barrier(int* lsense) {
    __syncthreads();
    if (threadIdx.x == 0) {
        int s = *lsense ^ 1;
        __threadfence();
        if (atomicAdd(&g_bar_count, 1) == NCTA - 1) {
            g_bar_count = 0;
            __threadfence();
            atomicExch(&g_bar_sense, s);
        } else {
            while (atomicAdd(&g_bar_sense, 0) != s) { }
        }
        *lsense = s;
        __threadfence();
    }
    __syncthreads();
}

__global__ __launch_bounds__(256)
void gru_scan_kernel(const float* __restrict__ h_init,
                     const float* __restrict__ Whh,
                     const float* __restrict__ bhh,
                     const float* __restrict__ xg,
                     int zero0,
                     float* __restrict__ hpair,
                     float* __restrict__ y) {
    extern __shared__ float h_s[];   // [H_][B_] 128 KB
    __shared__ int lsense;

    const int tid = threadIdx.x;
    const int b = tid & 31;
    const int j = (blockIdx.x << 3) + (tid >> 5);

    if (tid == 0) lsense = atomicAdd(&g_bar_sense, 0);
    __syncthreads();

    const float* wr = Whh + (size_t)j * H_;
    const float* wz = Whh + (size_t)(H_ + j) * H_;
    const float* wn = Whh + (size_t)(2 * H_ + j) * H_;
    const float br = bhh[j];
    const float bz = bhh[H_ + j];
    const float bnn = bhh[2 * H_ + j];

    for (int t = 0; t < S_; t++) {
        float accr = br, accz = bz, accn = bnn;
        float h_old = 0.f;
        const int skip = (t == 0) && zero0;

        if (!skip) {
            const float* hin = (t == 0) ? h_init : (hpair + (t & 1) * BH);
            for (int i4 = tid; i4 < BH / 4; i4 += 256) {
                int lin = i4 * 4;
                int bb = lin >> 10;
                int kk = lin & (H_ - 1);
                float4 v = *(const float4*)(hin + lin);
                h_s[(kk + 0) * B_ + bb] = v.x;
                h_s[(kk + 1) * B_ + bb] = v.y;
                h_s[(kk + 2) * B_ + bb] = v.z;
                h_s[(kk + 3) * B_ + bb] = v.w;
            }
            __syncthreads();

#pragma unroll 8
            for (int k = 0; k < H_; k += 4) {
                float4 r4 = __ldg((const float4*)(wr + k));
                float4 z4 = __ldg((const float4*)(wz + k));
                float4 n4 = __ldg((const float4*)(wn + k));
                float h0 = h_s[(k + 0) * B_ + b];
                float h1 = h_s[(k + 1) * B_ + b];
                float h2 = h_s[(k + 2) * B_ + b];
                float h3 = h_s[(k + 3) * B_ + b];
                accr += h0 * r4.x + h1 * r4.y + h2 * r4.z + h3 * r4.w;
                accz += h0 * z4.x + h1 * z4.y + h2 * z4.z + h3 * z4.w;
                accn += h0 * n4.x + h1 * n4.y + h2 * n4.z + h3 * n4.w;
            }
            h_old = h_s[j * B_ + b];
        }

        const float* xp = xg + ((size_t)b * S_ + t) * G3H;
        float r = 1.f / (1.f + expf(-(xp[j] + accr)));
        float z = 1.f / (1.f + expf(-(xp[H_ + j] + accz)));
        float n = tanhf(xp[2 * H_ + j] + r * accn);
        float hnew = (1.f - z) * n + z * h_old;

        hpair[((t + 1) & 1) * BH + b * H_ + j] = hnew;
        if (y) y[((size_t)b * S_ + t) * H_ + j] = hnew;

        grid_barrier(&lsense);
    }
}

// ---------------- driver ----------------
// K=512 GEMM: single pass Kc=Kw=512 (measured 218us regime)
static void gemm512(const float* Aact, const float* W, const float* bias,
                    float* Cout, float* AT, int M, int N) {
    dim3 tpb(32, 8);
    transpose_kernel<<<dim3(E_ / 32, M / 32), tpb>>>(Aact, AT, M, E_);
    gemm_ls_kernel<<<dim3(M / 128, N / 64), 256, GEMM_SMEM>>>(
        AT, W, bias, Cout, M, N, 512, 512, 0);
}

// K=1024 over repacked [2][N][512]: 8 passes of Kc=128/Kw=512 (probe regime, 32 TF/s)
static void gemm1024_k128(const float* Aact, const float* W2, const float* bias,
                          float* Cout, float* AT, int M, int N) {
    dim3 tpb(32, 8);
    transpose_kernel<<<dim3(H_ / 32, M / 32), tpb>>>(Aact, AT, M, H_);
    dim3 grid(M / 128, N / 64);
    for (int ko = 0; ko < H_; ko += 128) {
        int h = ko >> 9;
        int kin = ko & 511;
        gemm_ls_kernel<<<grid, 256, GEMM_SMEM>>>(
            AT + (size_t)ko * M,
            W2 + (size_t)h * N * 512 + kin,
            bias, Cout, M, N, 128, 512, ko > 0);
    }
}

extern "C" void kernel_launch(void* const* d_in, const int* in_sizes, int n_in,
                              void* d_out, int out_size) {
    const int*   enc_X   = (const int*)d_in[0];
    const int*   dec_X   = (const int*)d_in[1];
    const float* emb_enc = (const float*)d_in[2];
    const float* emb_dec = (const float*)d_in[3];
    const float* eW0i = (const float*)d_in[4];
    const float* eW0h = (const float*)d_in[5];
    const float* eb0i = (const float*)d_in[6];
    const float* eb0h = (const float*)d_in[7];
    const float* eW1i = (const float*)d_in[8];
    const float* eW1h = (const float*)d_in[9];
    const float* eb1i = (const float*)d_in[10];
    const float* eb1h = (const float*)d_in[11];
    const float* dW0i = (const float*)d_in[12];
    const float* dW0h = (const float*)d_in[13];
    const float* db0i = (const float*)d_in[14];
    const float* db0h = (const float*)d_in[15];
    const float* dW1i = (const float*)d_in[16];
    const float* dW1h = (const float*)d_in[17];
    const float* db1i = (const float*)d_in[18];
    const float* db1h = (const float*)d_in[19];
    const float* fcW  = (const float*)d_in[20];
    const float* fcb  = (const float*)d_in[21];
    float* out = (float*)d_out;

    float *ex, *dx, *xgA, *xgB, *seqA, *seqB, *hb, *AT, *WFC, *W2a, *W2b;
    cudaGetSymbolAddress((void**)&ex,   g_ex);
    cudaGetSymbolAddress((void**)&dx,   g_dx);
    cudaGetSymbolAddress((void**)&xgA,  g_xgA);
    cudaGetSymbolAddress((void**)&xgB,  g_xgB);
    cudaGetSymbolAddress((void**)&seqA, g_seqA);
    cudaGetSymbolAddress((void**)&seqB, g_seqB);
    cudaGetSymbolAddress((void**)&hb,   g_h);
    cudaGetSymbolAddress((void**)&AT,   g_AT);
    cudaGetSymbolAddress((void**)&WFC,  g_WFC);
    cudaGetSymbolAddress((void**)&W2a,  g_W2a);
    cudaGetSymbolAddress((void**)&W2b,  g_W2b);

    cudaFuncSetAttribute(gru_scan_kernel,
                         cudaFuncAttributeMaxDynamicSharedMemorySize, 131072);
    cudaFuncSetAttribute(gemm_ls_kernel,
                         cudaFuncAttributeMaxDynamicSharedMemorySize, GEMM_SMEM);

    float* hp0 = hb + 0 * 2 * BH;
    float* hp1 = hb + 1 * 2 * BH;
    float* hp2 = hb + 2 * 2 * BH;
    float* hp3 = hb + 3 * 2 * BH;

    // 0,1: embeds; 2: transpose ex; 3: enc0 xg GEMM <-- PROFILED guard
    embed_kernel<<<NTOK, 128>>>(enc_X, emb_enc, ex);
    embed_kernel<<<NTOK, 128>>>(dec_X, emb_dec, dx);
    gemm512(ex, eW0i, eb0i, xgA, AT, NTOK, G3H);

    // dec0 xg
    gemm512(dx, dW0i, db0i, xgB, AT, NTOK, G3H);

    // repacks (weight-only deps)
    repack_kernel<<<(int)(((size_t)V_ * H_ / 4) / 256), 256>>>(fcW, WFC, V_, H_);
    repack_kernel<<<(int)(((size_t)G3H * H_ / 4) / 256), 256>>>(eW1i, W2a, G3H, H_);
    repack_kernel<<<(int)(((size_t)G3H * H_ / 4) / 256), 256>>>(dW1i, W2b, G3H, H_);

    // enc0 scan (persistent; y -> seqA, final h -> hp0 buf0)
    gru_scan_kernel<<<NCTA, 256, 131072>>>(nullptr, eW0h, eb0h, xgA, 1, hp0, seqA);

    // enc1 xg (8 passes Kc=128 over repacked)
    gemm1024_k128(seqA, W2a, eb1i, xgA, AT, NTOK, G3H);

    // enc1 scan (persistent, zero init, no y)
    gru_scan_kernel<<<NCTA, 256, 131072>>>(nullptr, eW1h, eb1h, xgA, 1, hp1, nullptr);

    // dec0 scan (persistent, init = enc0 final h, y -> seqA)
    gru_scan_kernel<<<NCTA, 256, 131072>>>(hp0, dW0h, db0h, xgB, 0, hp2, seqA);

    // dec1 xg (8 passes Kc=128) + scan
    gemm1024_k128(seqA, W2b, db1i, xgA, AT, NTOK, G3H);
    gru_scan_kernel<<<NCTA, 256, 131072>>>(hp1, dW1h, db1h, xgA, 0, hp3, seqB);

    // final projection: 8 passes of Kc=128 (each = the measured 520us probe)
    gemm1024_k128(seqB, WFC, fcb, out, AT, NTOK, V_);
}

// round 16
// speedup vs baseline: 1.0908x; 1.0908x over previous
#include <cuda_runtime.h>
#include <math.h>
#include <stdint.h>

#define B_   32
#define S_   64
#define E_   512
#define H_   1024
#define V_   32000
#define G3H  (3 * H_)
#define NTOK (B_ * S_)
#define BH   (B_ * H_)
#define NCTA 128

// ---------------- scratch (device globals; no allocation allowed) ----------------
__device__ float g_ex[NTOK * E_];
__device__ float g_dx[NTOK * E_];
__device__ float g_xgA[NTOK * G3H];
__device__ float g_xgB[NTOK * G3H];
__device__ float g_seqA[NTOK * H_];
__device__ float g_seqB[NTOK * H_];
__device__ float g_h[8][BH];
__device__ float g_AT[NTOK * H_];    // transposed activations [K][M]

// grid-barrier state (zero-init; even barrier count per launch -> self-restoring)
__device__ int g_bar_count;
__device__ int g_bar_sense;

// ---------------- embedding gather ----------------
__global__ void embed_kernel(const int* __restrict__ idx,
                             const float* __restrict__ emb,
                             float* __restrict__ out) {
    int tok = blockIdx.x;
    int row = idx[tok];
    const float4* src = (const float4*)(emb + (size_t)row * E_);
    float4* dst = (float4*)(out + (size_t)tok * E_);
    for (int i = threadIdx.x; i < E_ / 4; i += blockDim.x) dst[i] = src[i];
}

// ---------------- transpose: out[C][R] = in[R][C]^T ----------------
__global__ __launch_bounds__(256)
void transpose_kernel(const float* __restrict__ in, float* __restrict__ out,
                      int R, int C) {
    __shared__ float t[32][33];
    const int c0 = blockIdx.x * 32;
    const int r0 = blockIdx.y * 32;
    const int x = threadIdx.x;
    const int y = threadIdx.y;
#pragma unroll
    for (int i = 0; i < 32; i += 8)
        t[y + i][x] = in[(size_t)(r0 + y + i) * C + c0 + x];
    __syncthreads();
#pragma unroll
    for (int i = 0; i < 32; i += 8)
        out[(size_t)(c0 + y + i) * R + r0 + x] = t[x][y + i];
}

// ---------------- GEMM (76 regs, measured 29-32 TF/s) ----------------
#define GKT 128
#define GEMM_SMEM (GKT * 128 * 4)

__global__ __launch_bounds__(256)
void gemm_ls_kernel(const float* __restrict__ AT,
                    const float* __restrict__ W,
                    const float* __restrict__ bias,
                    float* __restrict__ C,
                    int M, int N, int Kc, int Kw, int accum) {
    extern __shared__ float As[];   // [GKT][128]

    const int tid  = threadIdx.x;
    const int warp = tid >> 5;
    const int lane = tid & 31;
    const int bm = blockIdx.x * 128;
    const int bn = blockIdx.y * 64;
    const int n0 = bn + warp * 8;
    const int ml = lane * 4;

    float acc[8][4];
#pragma unroll
    for (int i = 0; i < 8; i++)
#pragma unroll
        for (int m = 0; m < 4; m++) acc[i][m] = 0.f;

    const int srow = tid >> 5;
    const int scol = lane << 2;

    const float* w0p = W + (size_t)(n0 + 0) * Kw;
    const float* w1p = W + (size_t)(n0 + 1) * Kw;
    const float* w2p = W + (size_t)(n0 + 2) * Kw;
    const float* w3p = W + (size_t)(n0 + 3) * Kw;
    const float* w4p = W + (size_t)(n0 + 4) * Kw;
    const float* w5p = W + (size_t)(n0 + 5) * Kw;
    const float* w6p = W + (size_t)(n0 + 6) * Kw;
    const float* w7p = W + (size_t)(n0 + 7) * Kw;

    for (int kt = 0; kt < Kc; kt += GKT) {
        __syncthreads();
#pragma unroll
        for (int i = 0; i < 16; i++) {
            int r = srow + i * 8;
            *(float4*)&As[r * 128 + scol] =
                *(const float4*)&AT[(size_t)(kt + r) * M + bm + scol];
        }
        __syncthreads();

#pragma unroll 2
        for (int k4 = 0; k4 < GKT; k4 += 4) {
            float a0[4], a1[4], a2[4], a3[4];
            *(float4*)a0 = *(const float4*)&As[(k4 + 0) * 128 + ml];
            *(float4*)a1 = *(const float4*)&As[(k4 + 1) * 128 + ml];
            *(float4*)a2 = *(const float4*)&As[(k4 + 2) * 128 + ml];
            *(float4*)a3 = *(const float4*)&As[(k4 + 3) * 128 + ml];
            const int ko = kt + k4;

            float4 w0 = __ldg((const float4*)(w0p + ko));
            float4 w1 = __ldg((const float4*)(w1p + ko));
            float4 w2 = __ldg((const float4*)(w2p + ko));
            float4 w3 = __ldg((const float4*)(w3p + ko));
#pragma unroll
            for (int m = 0; m < 4; m++) {
                acc[0][m] += w0.x * a0[m] + w0.y * a1[m] + w0.z * a2[m] + w0.w * a3[m];
                acc[1][m] += w1.x * a0[m] + w1.y * a1[m] + w1.z * a2[m] + w1.w * a3[m];
                acc[2][m] += w2.x * a0[m] + w2.y * a1[m] + w2.z * a2[m] + w2.w * a3[m];
                acc[3][m] += w3.x * a0[m] + w3.y * a1[m] + w3.z * a2[m] + w3.w * a3[m];
            }
            float4 w4 = __ldg((const float4*)(w4p + ko));
            float4 w5 = __ldg((const float4*)(w5p + ko));
            float4 w6 = __ldg((const float4*)(w6p + ko));
            float4 w7 = __ldg((const float4*)(w7p + ko));
#pragma unroll
            for (int m = 0; m < 4; m++) {
                acc[4][m] += w4.x * a0[m] + w4.y * a1[m] + w4.z * a2[m] + w4.w * a3[m];
                acc[5][m] += w5.x * a0[m] + w5.y * a1[m] + w5.z * a2[m] + w5.w * a3[m];
                acc[6][m] += w6.x * a0[m] + w6.y * a1[m] + w6.z * a2[m] + w6.w * a3[m];
                acc[7][m] += w7.x * a0[m] + w7.y * a1[m] + w7.z * a2[m] + w7.w * a3[m];
            }
        }
    }

    if (!accum) {
        float4 bv0 = *(const float4*)(bias + n0);
        float4 bv1 = *(const float4*)(bias + n0 + 4);
#pragma unroll
        for (int m = 0; m < 4; m++) {
            int mr = bm + ml + m;
            float4 o0, o1;
            o0.x = acc[0][m] + bv0.x; o0.y = acc[1][m] + bv0.y;
            o0.z = acc[2][m] + bv0.z; o0.w = acc[3][m] + bv0.w;
            o1.x = acc[4][m] + bv1.x; o1.y = acc[5][m] + bv1.y;
            o1.z = acc[6][m] + bv1.z; o1.w = acc[7][m] + bv1.w;
            *(float4*)(C + (size_t)mr * N + n0)     = o0;
            *(float4*)(C + (size_t)mr * N + n0 + 4) = o1;
        }
    } else {
#pragma unroll
        for (int m = 0; m < 4; m++) {
            int mr = bm + ml + m;
            float4 c0 = *(const float4*)(C + (size_t)mr * N + n0);
            float4 c1 = *(const float4*)(C + (size_t)mr * N + n0 + 4);
            c0.x += acc[0][m]; c0.y += acc[1][m];
            c0.z += acc[2][m]; c0.w += acc[3][m];
            c1.x += acc[4][m]; c1.y += acc[5][m];
            c1.z += acc[6][m]; c1.w += acc[7][m];
            *(float4*)(C + (size_t)mr * N + n0)     = c0;
            *(float4*)(C + (size_t)mr * N + n0 + 4) = c1;
        }
    }
}

// ---------------- persistent GRU scan with FAST grid barrier ----------------
// Arrive: ONE atomic per CTA. Spin: plain ld.volatile (broadcast L2 reads, no
// atomic-unit serialization — the R14/R15 barrier spun on atomicAdd(&sense,0),
// convoying 127 serializing atomics per step on one line).
__device__ __forceinline__ void grid_barrier(int* lsense) {
    __syncthreads();                       // all CTA stores issued before arrive
    if (threadIdx.x == 0) {
        int s = *lsense ^ 1;
        __threadfence();                   // publish this CTA's h writes
        if (atomicAdd(&g_bar_count, 1) == NCTA - 1) {
            g_bar_count = 0;
            __threadfence();
            atomicExch(&g_bar_sense, s);   // release
        } else {
            while (*(volatile int*)&g_bar_sense != s) { }   // cheap poll
        }
        *lsense = s;
        __threadfence();                   // acquire
    }
    __syncthreads();
}

__global__ __launch_bounds__(256)
void gru_scan_kernel(const float* __restrict__ h_init,
                     const float* __restrict__ Whh,
                     const float* __restrict__ bhh,
                     const float* __restrict__ xg,
                     int zero0,
                     float* __restrict__ hpair,
                     float* __restrict__ y) {
    extern __shared__ float h_s[];   // [H_][B_] 128 KB
    __shared__ int lsense_s;

    const int tid = threadIdx.x;
    const int b = tid & 31;
    const int j = (blockIdx.x << 3) + (tid >> 5);

    if (tid == 0) lsense_s = *(volatile int*)&g_bar_sense;
    __syncthreads();
    int lsense = lsense_s;

    const float* wr = Whh + (size_t)j * H_;
    const float* wz = Whh + (size_t)(H_ + j) * H_;
    const float* wn = Whh + (size_t)(2 * H_ + j) * H_;
    const float br = bhh[j];
    const float bz = bhh[H_ + j];
    const float bnn = bhh[2 * H_ + j];

    for (int t = 0; t < S_; t++) {
        float accr = br, accz = bz, accn = bnn;
        float h_old = 0.f;
        const int skip = (t == 0) && zero0;

        if (!skip) {
            const float* hin = (t == 0) ? h_init : (hpair + (t & 1) * BH);
            for (int i4 = tid; i4 < BH / 4; i4 += 256) {
                int lin = i4 * 4;
                int bb = lin >> 10;
                int kk = lin & (H_ - 1);
                float4 v = *(const float4*)(hin + lin);
                h_s[(kk + 0) * B_ + bb] = v.x;
                h_s[(kk + 1) * B_ + bb] = v.y;
                h_s[(kk + 2) * B_ + bb] = v.z;
                h_s[(kk + 3) * B_ + bb] = v.w;
            }
            __syncthreads();

#pragma unroll 8
            for (int k = 0; k < H_; k += 4) {
                float4 r4 = __ldg((const float4*)(wr + k));
                float4 z4 = __ldg((const float4*)(wz + k));
                float4 n4 = __ldg((const float4*)(wn + k));
                float h0 = h_s[(k + 0) * B_ + b];
                float h1 = h_s[(k + 1) * B_ + b];
                float h2 = h_s[(k + 2) * B_ + b];
                float h3 = h_s[(k + 3) * B_ + b];
                accr += h0 * r4.x + h1 * r4.y + h2 * r4.z + h3 * r4.w;
                accz += h0 * z4.x + h1 * z4.y + h2 * z4.z + h3 * z4.w;
                accn += h0 * n4.x + h1 * n4.y + h2 * n4.z + h3 * n4.w;
            }
            h_old = h_s[j * B_ + b];
        }

        const float* xp = xg + ((size_t)b * S_ + t) * G3H;
        float r = 1.f / (1.f + expf(-(xp[j] + accr)));
        float z = 1.f / (1.f + expf(-(xp[H_ + j] + accz)));
        float n = tanhf(xp[2 * H_ + j] + r * accn);
        float hnew = (1.f - z) * n + z * h_old;

        hpair[((t + 1) & 1) * BH + b * H_ + j] = hnew;
        if (y) y[((size_t)b * S_ + t) * H_ + j] = hnew;

        grid_barrier(&lsense);
    }
}

// ---------------- driver ----------------
static void gemm_full(const float* Aact, const float* W, const float* bias,
                      float* Cout, float* AT, int M, int N, int K) {
    dim3 tpb(32, 8);
    transpose_kernel<<<dim3(K / 32, M / 32), tpb>>>(Aact, AT, M, K);
    gemm_ls_kernel<<<dim3(M / 128, N / 64), 256, GEMM_SMEM>>>(
        AT, W, bias, Cout, M, N, K, K, 0);
}

extern "C" void kernel_launch(void* const* d_in, const int* in_sizes, int n_in,
                              void* d_out, int out_size) {
    const int*   enc_X   = (const int*)d_in[0];
    const int*   dec_X   = (const int*)d_in[1];
    const float* emb_enc = (const float*)d_in[2];
    const float* emb_dec = (const float*)d_in[3];
    const float* eW0i = (const float*)d_in[4];
    const float* eW0h = (const float*)d_in[5];
    const float* eb0i = (const float*)d_in[6];
    const float* eb0h = (const float*)d_in[7];
    const float* eW1i = (const float*)d_in[8];
    const float* eW1h = (const float*)d_in[9];
    const float* eb1i = (const float*)d_in[10];
    const float* eb1h = (const float*)d_in[11];
    const float* dW0i = (const float*)d_in[12];
    const float* dW0h = (const float*)d_in[13];
    const float* db0i = (const float*)d_in[14];
    const float* db0h = (const float*)d_in[15];
    const float* dW1i = (const float*)d_in[16];
    const float* dW1h = (const float*)d_in[17];
    const float* db1i = (const float*)d_in[18];
    const float* db1h = (const float*)d_in[19];
    const float* fcW  = (const float*)d_in[20];
    const float* fcb  = (const float*)d_in[21];
    float* out = (float*)d_out;

    float *ex, *dx, *xgA, *xgB, *seqA, *seqB, *hb, *AT;
    cudaGetSymbolAddress((void**)&ex,   g_ex);
    cudaGetSymbolAddress((void**)&dx,   g_dx);
    cudaGetSymbolAddress((void**)&xgA,  g_xgA);
    cudaGetSymbolAddress((void**)&xgB,  g_xgB);
    cudaGetSymbolAddress((void**)&seqA, g_seqA);
    cudaGetSymbolAddress((void**)&seqB, g_seqB);
    cudaGetSymbolAddress((void**)&hb,   g_h);
    cudaGetSymbolAddress((void**)&AT,   g_AT);

    cudaFuncSetAttribute(gru_scan_kernel,
                         cudaFuncAttributeMaxDynamicSharedMemorySize, 131072);
    cudaFuncSetAttribute(gemm_ls_kernel,
                         cudaFuncAttributeMaxDynamicSharedMemorySize, GEMM_SMEM);

    float* hp0 = hb + 0 * 2 * BH;
    float* hp1 = hb + 1 * 2 * BH;
    float* hp2 = hb + 2 * 2 * BH;
    float* hp3 = hb + 3 * 2 * BH;

    // [0] enc embed, [1] transpose ex, [2] enc0 xg GEMM,
    // [3] enc0 SCAN <-- PROFILED by ncu (-s 5 = 2 harness + index 3)
    embed_kernel<<<NTOK, 128>>>(enc_X, emb_enc, ex);
    gemm_full(ex, eW0i, eb0i, xgA, AT, NTOK, G3H, E_);
    gru_scan_kernel<<<NCTA, 256, 131072>>>(nullptr, eW0h, eb0h, xgA, 1, hp0, seqA);

    // dec embed + dec0 xg
    embed_kernel<<<NTOK, 128>>>(dec_X, emb_dec, dx);
    gemm_full(dx, dW0i, db0i, xgB, AT, NTOK, G3H, E_);

    // enc1 xg (consumes seqA)
    gemm_full(seqA, eW1i, eb1i, xgA, AT, NTOK, G3H, H_);

    // enc1 scan (zero init, no y)
    gru_scan_kernel<<<NCTA, 256, 131072>>>(nullptr, eW1h, eb1h, xgA, 1, hp1, nullptr);

    // dec0 scan (init = enc0 final h, y -> seqA)
    gru_scan_kernel<<<NCTA, 256, 131072>>>(hp0, dW0h, db0h, xgB, 0, hp2, seqA);

    // dec1 xg + scan
    gemm_full(seqA, dW1i, db1i, xgA, AT, NTOK, G3H, H_);
    gru_scan_kernel<<<NCTA, 256, 131072>>>(hp1, dW1h, db1h, xgA, 0, hp3, seqB);

    // final projection to vocab
    gemm_full(seqB, fcW, fcb, out, AT, NTOK, V_, H_);
}

// round 17
// speedup vs baseline: 1.1371x; 1.0425x over previous
#include <cuda_runtime.h>
#include <math.h>
#include <stdint.h>

#define B_   32
#define S_   64
#define E_   512
#define H_   1024
#define V_   32000
#define G3H  (3 * H_)
#define NTOK (B_ * S_)
#define BH   (B_ * H_)
#define NCTA 128

// ---------------- scratch (device globals; no allocation allowed) ----------------
__device__ float g_ex[NTOK * E_];
__device__ float g_dx[NTOK * E_];
__device__ float g_xgA[NTOK * G3H];
__device__ float g_xgB[NTOK * G3H];
__device__ float g_seqA[NTOK * H_];
__device__ float g_seqB[NTOK * H_];
__device__ float g_h[8][BH];

// grid-barrier state (zero-init; even barrier count per launch -> self-restoring)
__device__ int g_bar_count;
__device__ int g_bar_sense;

// ---------------- embedding gather ----------------
__global__ void embed_kernel(const int* __restrict__ idx,
                             const float* __restrict__ emb,
                             float* __restrict__ out) {
    int tok = blockIdx.x;
    int row = idx[tok];
    const float4* src = (const float4*)(emb + (size_t)row * E_);
    float4* dst = (float4*)(out + (size_t)tok * E_);
    for (int i = threadIdx.x; i < E_ / 4; i += blockDim.x) dst[i] = src[i];
}

// ---------------- R1 champion SGEMM: C[M,N] = A[M,K]*W[N,K]^T + bias ----------------
// Both operands K-major, staged+transposed through smem. 128x128 tile, BK=8,
// 256 threads, 8x8/thread. EXACT kernel from the 16.63ms champion round.
#define BM 128
#define BN 128
#define BK 8

__global__ __launch_bounds__(256)
void sgemm_kernel(const float* __restrict__ A,
                  const float* __restrict__ W,
                  const float* __restrict__ bias,
                  float* __restrict__ C,
                  int M, int N, int K) {
    __shared__ float As[BK][BM];
    __shared__ float Bs[BK][BN];

    const int tid = threadIdx.x;
    const int bm = blockIdx.y * BM;
    const int bn = blockIdx.x * BN;

    const int lr = tid >> 1;          // 0..127 : row within tile
    const int lk = (tid & 1) * 4;     // 0 or 4 : k quad

    const int tx = tid & 15;          // 0..15
    const int ty = tid >> 4;          // 0..15

    float acc[8][8];
#pragma unroll
    for (int i = 0; i < 8; i++)
#pragma unroll
        for (int j = 0; j < 8; j++) acc[i][j] = 0.f;

    const float* Aptr = A + (size_t)(bm + lr) * K + lk;
    const float* Wptr = W + (size_t)(bn + lr) * K + lk;

    for (int k0 = 0; k0 < K; k0 += BK) {
        float4 av = *(const float4*)(Aptr + k0);
        float4 bv = *(const float4*)(Wptr + k0);
        As[lk + 0][lr] = av.x; As[lk + 1][lr] = av.y;
        As[lk + 2][lr] = av.z; As[lk + 3][lr] = av.w;
        Bs[lk + 0][lr] = bv.x; Bs[lk + 1][lr] = bv.y;
        Bs[lk + 2][lr] = bv.z; Bs[lk + 3][lr] = bv.w;
        __syncthreads();

#pragma unroll
        for (int k = 0; k < BK; k++) {
            float a[8], b[8];
            *(float4*)&a[0] = *(const float4*)&As[k][ty * 4];
            *(float4*)&a[4] = *(const float4*)&As[k][64 + ty * 4];
            *(float4*)&b[0] = *(const float4*)&Bs[k][tx * 4];
            *(float4*)&b[4] = *(const float4*)&Bs[k][64 + tx * 4];
#pragma unroll
            for (int i = 0; i < 8; i++)
#pragma unroll
                for (int j = 0; j < 8; j++) acc[i][j] += a[i] * b[j];
        }
        __syncthreads();
    }

    // epilogue: bias add + vectorized stores
#pragma unroll
    for (int i = 0; i < 8; i++) {
        int m = bm + ((i < 4) ? (ty * 4 + i) : (64 + ty * 4 + (i - 4)));
#pragma unroll
        for (int half = 0; half < 2; half++) {
            int n = bn + half * 64 + tx * 4;
            float4 bvv = *(const float4*)(bias + n);
            float4 o;
            o.x = acc[i][half * 4 + 0] + bvv.x;
            o.y = acc[i][half * 4 + 1] + bvv.y;
            o.z = acc[i][half * 4 + 2] + bvv.z;
            o.w = acc[i][half * 4 + 3] + bvv.w;
            *(float4*)(C + (size_t)m * N + n) = o;
        }
    }
}

// ---------------- persistent GRU scan (R16 kernel verbatim) ----------------
__device__ __forceinline__ void grid_barrier(int* lsense) {
    __syncthreads();
    if (threadIdx.x == 0) {
        int s = *lsense ^ 1;
        __threadfence();
        if (atomicAdd(&g_bar_count, 1) == NCTA - 1) {
            g_bar_count = 0;
            __threadfence();
            atomicExch(&g_bar_sense, s);
        } else {
            while (*(volatile int*)&g_bar_sense != s) { }
        }
        *lsense = s;
        __threadfence();
    }
    __syncthreads();
}

__global__ __launch_bounds__(256)
void gru_scan_kernel(const float* __restrict__ h_init,
                     const float* __restrict__ Whh,
                     const float* __restrict__ bhh,
                     const float* __restrict__ xg,
                     int zero0,
                     float* __restrict__ hpair,
                     float* __restrict__ y) {
    extern __shared__ float h_s[];   // [H_][B_] 128 KB
    __shared__ int lsense_s;

    const int tid = threadIdx.x;
    const int b = tid & 31;
    const int j = (blockIdx.x << 3) + (tid >> 5);

    if (tid == 0) lsense_s = *(volatile int*)&g_bar_sense;
    __syncthreads();
    int lsense = lsense_s;

    const float* wr = Whh + (size_t)j * H_;
    const float* wz = Whh + (size_t)(H_ + j) * H_;
    const float* wn = Whh + (size_t)(2 * H_ + j) * H_;
    const float br = bhh[j];
    const float bz = bhh[H_ + j];
    const float bnn = bhh[2 * H_ + j];

    for (int t = 0; t < S_; t++) {
        float accr = br, accz = bz, accn = bnn;
        float h_old = 0.f;
        const int skip = (t == 0) && zero0;

        if (!skip) {
            const float* hin = (t == 0) ? h_init : (hpair + (t & 1) * BH);
            for (int i4 = tid; i4 < BH / 4; i4 += 256) {
                int lin = i4 * 4;
                int bb = lin >> 10;
                int kk = lin & (H_ - 1);
                float4 v = *(const float4*)(hin + lin);
                h_s[(kk + 0) * B_ + bb] = v.x;
                h_s[(kk + 1) * B_ + bb] = v.y;
                h_s[(kk + 2) * B_ + bb] = v.z;
                h_s[(kk + 3) * B_ + bb] = v.w;
            }
            __syncthreads();

#pragma unroll 8
            for (int k = 0; k < H_; k += 4) {
                float4 r4 = __ldg((const float4*)(wr + k));
                float4 z4 = __ldg((const float4*)(wz + k));
                float4 n4 = __ldg((const float4*)(wn + k));
                float h0 = h_s[(k + 0) * B_ + b];
                float h1 = h_s[(k + 1) * B_ + b];
                float h2 = h_s[(k + 2) * B_ + b];
                float h3 = h_s[(k + 3) * B_ + b];
                accr += h0 * r4.x + h1 * r4.y + h2 * r4.z + h3 * r4.w;
                accz += h0 * z4.x + h1 * z4.y + h2 * z4.z + h3 * z4.w;
                accn += h0 * n4.x + h1 * n4.y + h2 * n4.z + h3 * n4.w;
            }
            h_old = h_s[j * B_ + b];
        }

        const float* xp = xg + ((size_t)b * S_ + t) * G3H;
        float r = 1.f / (1.f + expf(-(xp[j] + accr)));
        float z = 1.f / (1.f + expf(-(xp[H_ + j] + accz)));
        float n = tanhf(xp[2 * H_ + j] + r * accn);
        float hnew = (1.f - z) * n + z * h_old;

        hpair[((t + 1) & 1) * BH + b * H_ + j] = hnew;
        if (y) y[((size_t)b * S_ + t) * H_ + j] = hnew;

        grid_barrier(&lsense);
    }
}

// ---------------- driver: 11 launches ----------------
extern "C" void kernel_launch(void* const* d_in, const int* in_sizes, int n_in,
                              void* d_out, int out_size) {
    const int*   enc_X   = (const int*)d_in[0];
    const int*   dec_X   = (const int*)d_in[1];
    const float* emb_enc = (const float*)d_in[2];
    const float* emb_dec = (const float*)d_in[3];
    const float* eW0i = (const float*)d_in[4];
    const float* eW0h = (const float*)d_in[5];
    const float* eb0i = (const float*)d_in[6];
    const float* eb0h = (const float*)d_in[7];
    const float* eW1i = (const float*)d_in[8];
    const float* eW1h = (const float*)d_in[9];
    const float* eb1i = (const float*)d_in[10];
    const float* eb1h = (const float*)d_in[11];
    const float* dW0i = (const float*)d_in[12];
    const float* dW0h = (const float*)d_in[13];
    const float* db0i = (const float*)d_in[14];
    const float* db0h = (const float*)d_in[15];
    const float* dW1i = (const float*)d_in[16];
    const float* dW1h = (const float*)d_in[17];
    const float* db1i = (const float*)d_in[18];
    const float* db1h = (const float*)d_in[19];
    const float* fcW  = (const float*)d_in[20];
    const float* fcb  = (const float*)d_in[21];
    float* out = (float*)d_out;

    float *ex, *dx, *xgA, *xgB, *seqA, *seqB, *hb;
    cudaGetSymbolAddress((void**)&ex,   g_ex);
    cudaGetSymbolAddress((void**)&dx,   g_dx);
    cudaGetSymbolAddress((void**)&xgA,  g_xgA);
    cudaGetSymbolAddress((void**)&xgB,  g_xgB);
    cudaGetSymbolAddress((void**)&seqA, g_seqA);
    cudaGetSymbolAddress((void**)&seqB, g_seqB);
    cudaGetSymbolAddress((void**)&hb,   g_h);

    cudaFuncSetAttribute(gru_scan_kernel,
                         cudaFuncAttributeMaxDynamicSharedMemorySize, 131072);

    float* hp0 = hb + 0 * 2 * BH;
    float* hp1 = hb + 1 * 2 * BH;
    float* hp2 = hb + 2 * 2 * BH;
    float* hp3 = hb + 3 * 2 * BH;

    dim3 g3h(G3H / BN, NTOK / BM);   // R1 grid order

    // [0] enc embed, [1] dec embed, [2] enc0 xg,
    // [3] dec0 xg <-- PROFILED (first direct measurement of the R1 GEMM)
    embed_kernel<<<NTOK, 128>>>(enc_X, emb_enc, ex);
    embed_kernel<<<NTOK, 128>>>(dec_X, emb_dec, dx);
    sgemm_kernel<<<g3h, 256>>>(ex, eW0i, eb0i, xgA, NTOK, G3H, E_);
    sgemm_kernel<<<g3h, 256>>>(dx, dW0i, db0i, xgB, NTOK, G3H, E_);

    // [4] enc0 scan (persistent; y -> seqA, final h -> hp0 buf0)
    gru_scan_kernel<<<NCTA, 256, 131072>>>(nullptr, eW0h, eb0h, xgA, 1, hp0, seqA);

    // [5] enc1 xg
    sgemm_kernel<<<g3h, 256>>>(seqA, eW1i, eb1i, xgA, NTOK, G3H, H_);

    // [6] enc1 scan (zero init, no y)
    gru_scan_kernel<<<NCTA, 256, 131072>>>(nullptr, eW1h, eb1h, xgA, 1, hp1, nullptr);

    // [7] dec0 scan (init = enc0 final h, y -> seqA)
    gru_scan_kernel<<<NCTA, 256, 131072>>>(hp0, dW0h, db0h, xgB, 0, hp2, seqA);

    // [8] dec1 xg, [9] dec1 scan (init = enc1 final h, y -> seqB)
    sgemm_kernel<<<g3h, 256>>>(seqA, dW1i, db1i, xgA, NTOK, G3H, H_);
    gru_scan_kernel<<<NCTA, 256, 131072>>>(hp1, dW1h, db1h, xgA, 0, hp3, seqB);

    // [10] final projection to vocab
    dim3 fc(V_ / BN, NTOK / BM);
    sgemm_kernel<<<fc, 256>>>(seqB, fcW, fcb, out, NTOK, V_, H_);
}